// round 10
// baseline (speedup 1.0000x reference)
#include <cuda_runtime.h>
#include <cstdint>

#define T_STEPS 64
typedef unsigned long long u64;

// ---------------- packed f32x2 helpers ----------------
__device__ __forceinline__ u64 ffma2(u64 a, u64 b, u64 c){
  u64 d; asm("fma.rn.f32x2 %0, %1, %2, %3;" : "=l"(d) : "l"(a), "l"(b), "l"(c)); return d;
}
__device__ __forceinline__ u64 addf2(u64 a, u64 b){
  u64 d; asm("add.rn.f32x2 %0, %1, %2;" : "=l"(d) : "l"(a), "l"(b)); return d;
}
__device__ __forceinline__ u64 pack2(float lo, float hi){
  u64 d; asm("mov.b64 %0, {%1, %2};" : "=l"(d) : "f"(lo), "f"(hi)); return d;
}
__device__ __forceinline__ float lo2(u64 a){ return __uint_as_float((unsigned)a); }
__device__ __forceinline__ float hi2(u64 a){ return __uint_as_float((unsigned)(a >> 32)); }
__device__ __forceinline__ float hsum2(u64 a){ return lo2(a) + hi2(a); }
__device__ __forceinline__ float rcpa(float x){
  float r; asm("rcp.approx.f32 %0, %1;" : "=f"(r) : "f"(x)); return r;
}

#define BAR_ELEM(e) asm volatile("bar.sync %0, 128;" :: "r"((e)+1) : "memory")

// ---------------- repacked weights (loop-invariant, built by pre-kernel) ----------------
__device__ __align__(16) float gatP[49152];   // [l][k4][c][4] : gatW[l][4k4+i][c]
__device__ __align__(16) float WihP[65536];   // [k4][c][4]
__device__ __align__(16) float WhhP[65536];
__device__ __align__(16) float pW1P[8192];
__device__ __align__(16) float aW1P[8192];
__device__ __align__(16) float aW2P[2048];
__device__ __align__(16) float bsumP[512];    // b_ih + b_hh

__global__ void repack_kernel(const float* __restrict__ gatW, const float* __restrict__ W_ih,
                              const float* __restrict__ W_hh, const float* __restrict__ pW1,
                              const float* __restrict__ aW1,  const float* __restrict__ aW2,
                              const float* __restrict__ b_ih, const float* __restrict__ b_hh){
  for (int idx = blockIdx.x*blockDim.x + threadIdx.x; idx < 199168; idx += gridDim.x*blockDim.x){
    if (idx < 49152){
      int f = idx; int i = f&3, c = (f>>2)&127, k4 = (f>>9)&31, l = f>>14;
      gatP[f] = gatW[(l*128 + k4*4 + i)*128 + c];
    } else if (idx < 114688){
      int f = idx - 49152; int i = f&3, c = (f>>2)&511, k4 = f>>11;
      WihP[f] = W_ih[(k4*4+i)*512 + c];
    } else if (idx < 180224){
      int f = idx - 114688; int i = f&3, c = (f>>2)&511, k4 = f>>11;
      WhhP[f] = W_hh[(k4*4+i)*512 + c];
    } else if (idx < 188416){
      int f = idx - 180224; int i = f&3, c = (f>>2)&63, k4 = f>>8;
      pW1P[f] = pW1[(k4*4+i)*64 + c];
    } else if (idx < 196608){
      int f = idx - 188416; int i = f&3, c = (f>>2)&63, k4 = f>>8;
      aW1P[f] = aW1[(k4*4+i)*64 + c];
    } else if (idx < 198656){
      int f = idx - 196608; int i = f&3, c = (f>>2)&31, k4 = f>>7;
      aW2P[f] = aW2[(k4*4+i)*32 + c];
    } else {
      int f = idx - 198656;
      bsumP[f] = b_ih[f] + b_hh[f];
    }
  }
}

// ---------------- threefry2x32 (exact JAX, partitionable path) ----------------
__device__ __forceinline__ uint32_t rotl32(uint32_t x, int d){ return __funnelshift_l(x, x, d); }

__device__ __forceinline__ void threefry(uint32_t k0, uint32_t k1, uint32_t x0, uint32_t x1,
                                         uint32_t& o0, uint32_t& o1){
  uint32_t k2 = k0 ^ k1 ^ 0x1BD11BDAu;
  x0 += k0; x1 += k1;
  #define TFR(a,b,c,d) \
    x0 += x1; x1 = rotl32(x1,a); x1 ^= x0; \
    x0 += x1; x1 = rotl32(x1,b); x1 ^= x0; \
    x0 += x1; x1 = rotl32(x1,c); x1 ^= x0; \
    x0 += x1; x1 = rotl32(x1,d); x1 ^= x0;
  TFR(13,15,26,6)  x0 += k1; x1 += k2 + 1u;
  TFR(17,29,16,24) x0 += k2; x1 += k0 + 2u;
  TFR(13,15,26,6)  x0 += k0; x1 += k1 + 3u;
  TFR(17,29,16,24) x0 += k1; x1 += k2 + 4u;
  TFR(13,15,26,6)  x0 += k2; x1 += k0 + 5u;
  #undef TFR
  o0 = x0; o1 = x1;
}

// XLA ErfInv f32 (Giles polynomial)
__device__ __forceinline__ float erfinv_f(float x){
  float w = -__logf(fmaf(-x, x, 1.0f));
  float p;
  if (w < 5.0f){
    w -= 2.5f;
    p = 2.81022636e-08f;
    p = fmaf(p, w, 3.43273939e-07f);
    p = fmaf(p, w, -3.5233877e-06f);
    p = fmaf(p, w, -4.39150654e-06f);
    p = fmaf(p, w, 0.00021858087f);
    p = fmaf(p, w, -0.00125372503f);
    p = fmaf(p, w, -0.00417768164f);
    p = fmaf(p, w, 0.246640727f);
    p = fmaf(p, w, 1.50140941f);
  } else {
    w = sqrtf(w) - 3.0f;
    p = -0.000200214257f;
    p = fmaf(p, w, 0.000100950558f);
    p = fmaf(p, w, 0.00134934322f);
    p = fmaf(p, w, -0.00367342844f);
    p = fmaf(p, w, 0.00573950773f);
    p = fmaf(p, w, -0.0076224613f);
    p = fmaf(p, w, 0.00943887047f);
    p = fmaf(p, w, 1.00167406f);
    p = fmaf(p, w, 2.83297682f);
  }
  return p * x;
}

__device__ __forceinline__ float bits_to_normal(uint32_t bits){
  float f = __uint_as_float((bits >> 9) | 0x3f800000u) - 1.0f;
  const float lo = -0.99999994f;
  float u = fmaf(f, 2.0f, lo);
  u = fmaxf(u, lo);
  return 1.41421356237309515f * erfinv_f(u);
}

__device__ __forceinline__ float warpsum(float v){
  #pragma unroll
  for (int o = 16; o > 0; o >>= 1) v += __shfl_xor_sync(0xffffffffu, v, o);
  return v;
}
__device__ __forceinline__ u64 warpsum2(u64 v){
  #pragma unroll
  for (int o = 16; o > 0; o >>= 1){
    uint32_t l = (uint32_t)v, h = (uint32_t)(v >> 32);
    l = __shfl_xor_sync(0xffffffffu, l, o);
    h = __shfl_xor_sync(0xffffffffu, h, o);
    v = addf2(v, ((u64)h << 32) | l);
  }
  return v;
}
__device__ __forceinline__ float sig_(float x){ return rcpa(1.0f + __expf(-x)); }
__device__ __forceinline__ float tanh_(float x){ return fmaf(2.0f, rcpa(1.0f + __expf(-2.0f*x)), -1.0f); }

// ------- mega kernel: 1 block = 2 batch elems, 4 warps/elem, target 4 CTA/SM -------
__global__ __launch_bounds__(256, 4)
void vkc_kernel(
  const int*   __restrict__ gesture_idx,
  const float* __restrict__ demographics,
  const float* __restrict__ emb_table,
  const float* __restrict__ dW1, const float* __restrict__ db1,
  const float* __restrict__ dW2, const float* __restrict__ db2,
  const float* __restrict__ jiW, const float* __restrict__ jib,
  const float* __restrict__ gat_asrc,
  const float* __restrict__ gat_adst, const float* __restrict__ gat_b,
  const float* __restrict__ ln_g, const float* __restrict__ ln_b,
  const float* __restrict__ pb1,
  const float* __restrict__ pW2, const float* __restrict__ pb2,
  const float* __restrict__ ab1,
  const float* __restrict__ ab2,
  const float* __restrict__ aW3, const float* __restrict__ ab3,
  float* __restrict__ out)
{
  __shared__ __align__(16) float xs[6][128];    // x state: 2 elems x 3 joints
  __shared__ __align__(16) float UB[1024];      // union: xp rows / gates / combined, 512/elem
  __shared__ __align__(16) float hs[2][128];
  __shared__ __align__(16) float cs[2][128];
  __shared__ __align__(16) float scr[2][64];
  __shared__              float physs[2][3];

  const int tid  = threadIdx.x;
  const int w    = tid >> 5;       // warp 0..7
  const int lane = tid & 31;
  const int e    = w >> 2;         // local element 0..1
  const int wq   = w & 3;          // warp-quarter within element
  const int g    = blockIdx.x;     // 0..511
  const int b    = g*2 + e;
  const int wr   = e * 3;          // row base in xs
  const int q    = wq*32 + lane;   // 0..127: per-elem thread index
  float* const xpE = UB + e*512;
  float* const gtE = UB + e*512;

  // ---------------- setup: demo MLP + embedding -> combined ----------------
  if (q < 64){
    float dm[7];
    #pragma unroll
    for (int i = 0; i < 7; i++) dm[i] = demographics[b*7 + i];
    float a0 = db1[q];
    #pragma unroll
    for (int i = 0; i < 7; i++) a0 = fmaf(dm[i], dW1[i*64 + q], a0);
    scr[e][q] = fmaxf(a0, 0.f);
  }
  __syncthreads();
  {
    const int gi = gesture_idx[b];
    gtE[q] = emb_table[gi*128 + q];            // combined[0:128]
    float acc = db2[q];
    #pragma unroll 4
    for (int k = 0; k < 64; k++) acc = fmaf(scr[e][k], dW2[k*128 + q], acc);
    gtE[128 + q] = acc;                        // combined[128:256]
    hs[e][q] = 0.f; cs[e][q] = 0.f;
  }
  __syncthreads();

  // ---------------- jf = relu(combined @ jiW + jib) -> xs (per elem) ----------------
  {
    float a0 = 0.f, a1 = 0.f, a2 = 0.f;
    #pragma unroll 4
    for (int k = 0; k < 256; k++){
      float cv = gtE[k];
      a0 = fmaf(cv, jiW[0*32768 + k*128 + q], a0);
      a1 = fmaf(cv, jiW[1*32768 + k*128 + q], a1);
      a2 = fmaf(cv, jiW[2*32768 + k*128 + q], a2);
    }
    __syncthreads();   // gtE slot reused as xp next
    xs[wr+0][q] = fmaxf(a0 + jib[0*128 + q], 0.f);
    xs[wr+1][q] = fmaxf(a1 + jib[1*128 + q], 0.f);
    xs[wr+2][q] = fmaxf(a2 + jib[2*128 + q], 0.f);
  }
  __syncthreads();

  // ---------------- time loop ----------------
  for (int t = 0; t < T_STEPS; t++){
    // ===== 3 GAT layers (elem-local: 4 warps, 128 threads each) =====
    #pragma unroll 1
    for (int l = 0; l < 3; l++){
      // GEMM: thread q -> col q, rows 0..2
      {
        const float* Wl = gatP + l*16384;
        u64 a0 = 0ull, a1 = 0ull, a2 = 0ull;
        #pragma unroll 4
        for (int k4 = 0; k4 < 32; k4++){
          const ulonglong2 wv = *reinterpret_cast<const ulonglong2*>(Wl + (k4*128 + q)*4);
          const ulonglong2 x0 = *reinterpret_cast<const ulonglong2*>(&xs[wr+0][k4*4]);
          const ulonglong2 x1 = *reinterpret_cast<const ulonglong2*>(&xs[wr+1][k4*4]);
          const ulonglong2 x2 = *reinterpret_cast<const ulonglong2*>(&xs[wr+2][k4*4]);
          a0 = ffma2(x0.x, wv.x, a0); a0 = ffma2(x0.y, wv.y, a0);
          a1 = ffma2(x1.x, wv.x, a1); a1 = ffma2(x1.y, wv.y, a1);
          a2 = ffma2(x2.x, wv.x, a2); a2 = ffma2(x2.y, wv.y, a2);
        }
        xpE[0*128 + q] = hsum2(a0);
        xpE[1*128 + q] = hsum2(a1);
        xpE[2*128 + q] = hsum2(a2);
      }
      BAR_ELEM(e);

      // attention: 1 head per warp (head wq, cols wq*32+lane = q)
      {
        const float* as = gat_asrc + l*128;
        const float* ad = gat_adst + l*128;
        float x0v = xpE[0*128+q], x1v = xpE[1*128+q], x2v = xpE[2*128+q];
        float av = as[q], dv = ad[q];
        u64 S01 = warpsum2(pack2(x0v*av, x1v*av));
        u64 SD2 = warpsum2(pack2(x2v*av, x2v*dv));
        float d1 = warpsum(x1v*dv);
        float s0 = lo2(S01), s1 = hi2(S01), s2 = lo2(SD2), d2 = hi2(SD2);
        float e10 = d1+s0; e10 = e10 > 0.f ? e10 : 0.2f*e10;
        float e11 = d1+s1; e11 = e11 > 0.f ? e11 : 0.2f*e11;
        float e21 = d2+s1; e21 = e21 > 0.f ? e21 : 0.2f*e21;
        float e22 = d2+s2; e22 = e22 > 0.f ? e22 : 0.2f*e22;
        float m1 = fmaxf(e10, e11);
        float p10 = __expf(e10-m1), p11 = __expf(e11-m1);
        float i1 = rcpa(p10+p11);
        float m2 = fmaxf(e21, e22);
        float p21 = __expf(e21-m2), p22 = __expf(e22-m2);
        float i2 = rcpa(p21+p22);
        xpE[1*128+q] = (p10*x0v + p11*x1v)*i1;
        xpE[2*128+q] = (p21*x1v + p22*x2v)*i2;
      }
      BAR_ELEM(e);

      // bias + single-pass layernorm + relu + residual; row j = wq (wq<3)
      if (wq < 3){
        const int j = wq;
        float v[4];
        float s = 0.f, ss = 0.f;
        #pragma unroll
        for (int p = 0; p < 4; p++){
          int c = lane + 32*p;
          v[p] = xpE[j*128 + c] + gat_b[l*128 + c];
          s += v[p];
          ss = fmaf(v[p], v[p], ss);
        }
        u64 red = warpsum2(pack2(s, ss));
        float mu  = lo2(red) * (1.f/128.f);
        float var = fmaf(-mu, mu, hi2(red) * (1.f/128.f));
        float inv = rsqrtf(var + 1e-5f);
        #pragma unroll
        for (int p = 0; p < 4; p++){
          int c = lane + 32*p;
          float y = (v[p]-mu)*inv*ln_g[l*128 + c] + ln_b[l*128 + c];
          xs[wr+j][c] = fmaxf(y, 0.f) + xs[wr+j][c];
        }
      }
      BAR_ELEM(e);
    }

    __syncthreads();   // both elems' xs row2 + hs ready; xp slots dead -> gates

    // ===== LSTM gates GEMM: thread -> cols (tid, tid+256) x 2 elems =====
    {
      const int c  = tid;
      const int c2 = tid + 256;
      u64 aA0 = pack2(bsumP[c],  0.f), aB0 = pack2(bsumP[c2], 0.f);
      u64 aA1 = aA0, aB1 = aB0;
      #pragma unroll 2
      for (int k4 = 0; k4 < 32; k4++){
        const ulonglong2 wiA = *reinterpret_cast<const ulonglong2*>(WihP + (k4*512 + c )*4);
        const ulonglong2 wiB = *reinterpret_cast<const ulonglong2*>(WihP + (k4*512 + c2)*4);
        const ulonglong2 whA = *reinterpret_cast<const ulonglong2*>(WhhP + (k4*512 + c )*4);
        const ulonglong2 whB = *reinterpret_cast<const ulonglong2*>(WhhP + (k4*512 + c2)*4);
        {
          const ulonglong2 xv = *reinterpret_cast<const ulonglong2*>(&xs[2][k4*4]);
          const ulonglong2 hv = *reinterpret_cast<const ulonglong2*>(&hs[0][k4*4]);
          aA0 = ffma2(xv.x, wiA.x, aA0); aA0 = ffma2(xv.y, wiA.y, aA0);
          aA0 = ffma2(hv.x, whA.x, aA0); aA0 = ffma2(hv.y, whA.y, aA0);
          aB0 = ffma2(xv.x, wiB.x, aB0); aB0 = ffma2(xv.y, wiB.y, aB0);
          aB0 = ffma2(hv.x, whB.x, aB0); aB0 = ffma2(hv.y, whB.y, aB0);
        }
        {
          const ulonglong2 xv = *reinterpret_cast<const ulonglong2*>(&xs[5][k4*4]);
          const ulonglong2 hv = *reinterpret_cast<const ulonglong2*>(&hs[1][k4*4]);
          aA1 = ffma2(xv.x, wiA.x, aA1); aA1 = ffma2(xv.y, wiA.y, aA1);
          aA1 = ffma2(hv.x, whA.x, aA1); aA1 = ffma2(hv.y, whA.y, aA1);
          aB1 = ffma2(xv.x, wiB.x, aB1); aB1 = ffma2(xv.y, wiB.y, aB1);
          aB1 = ffma2(hv.x, whB.x, aB1); aB1 = ffma2(hv.y, whB.y, aB1);
        }
      }
      UB[0*512 + c]  = hsum2(aA0);
      UB[0*512 + c2] = hsum2(aB0);
      UB[1*512 + c]  = hsum2(aA1);
      UB[1*512 + c2] = hsum2(aB1);
    }
    __syncthreads();

    // ===== LSTM pointwise: thread q -> col q of its elem =====
    {
      float gi = gtE[q];
      float gf = gtE[128 + q];
      float gg = gtE[256 + q];
      float go = gtE[384 + q];
      float cn = sig_(gf)*cs[e][q] + sig_(gi)*tanh_(gg);
      float hn = sig_(go)*tanh_(cn);
      cs[e][q] = cn; hs[e][q] = hn;
    }

    // ===== noise (elem-local): x += 0.05 * normal * (t/64); skip t=0 and t=63 =====
    if (t >= 1 && t < T_STEPS - 1){
      const float scale = 0.05f * (float)t * (1.0f/64.0f);
      uint32_t kt0, kt1;
      threefry(0u, 42u, 0u, (uint32_t)t, kt0, kt1);
      #pragma unroll
      for (int r = 0; r < 3; r++){
        int ii = q + r*128;                   // j = r', covers 384
        uint32_t m = (uint32_t)(b*384 + ii);
        uint32_t o0, o1;
        threefry(kt0, kt1, 0u, m, o0, o1);
        xs[wr + r][q] += scale * bits_to_normal(o0 ^ o1);
      }
    }
    BAR_ELEM(e);   // hs + noised xs complete within element

    // ===== output heads: wq0 = phys path, wq1 = act path (wq2/3 idle) =====
    float t2 = 0.f;
    if (wq == 0){
      u64 pa = 0ull, pb = 0ull;
      #pragma unroll 4
      for (int k4 = 0; k4 < 32; k4++){
        const ulonglong2 wA = *reinterpret_cast<const ulonglong2*>(pW1P + (k4*64 + lane   )*4);
        const ulonglong2 wB = *reinterpret_cast<const ulonglong2*>(pW1P + (k4*64 + lane+32)*4);
        const ulonglong2 hv = *reinterpret_cast<const ulonglong2*>(&hs[e][k4*4]);
        pa = ffma2(hv.x, wA.x, pa); pa = ffma2(hv.y, wA.y, pa);
        pb = ffma2(hv.x, wB.x, pb); pb = ffma2(hv.y, wB.y, pb);
      }
      float p_a = fmaxf(hsum2(pa) + pb1[lane],    0.f);
      float p_b = fmaxf(hsum2(pb) + pb1[lane+32], 0.f);
      u64 P01 = warpsum2(pack2(p_a*pW2[lane*3+0] + p_b*pW2[(lane+32)*3+0],
                               p_a*pW2[lane*3+1] + p_b*pW2[(lane+32)*3+1]));
      float ph2 = warpsum(p_a*pW2[lane*3+2] + p_b*pW2[(lane+32)*3+2]);
      if (lane == 0){
        physs[e][0] = lo2(P01) + pb2[0];
        physs[e][1] = hi2(P01) + pb2[1];
        physs[e][2] = ph2      + pb2[2];
      }
    } else if (wq == 1){
      u64 aa = 0ull, ab = 0ull;
      #pragma unroll 4
      for (int k4 = 0; k4 < 32; k4++){
        const ulonglong2 wA = *reinterpret_cast<const ulonglong2*>(aW1P + (k4*64 + lane   )*4);
        const ulonglong2 wB = *reinterpret_cast<const ulonglong2*>(aW1P + (k4*64 + lane+32)*4);
        const ulonglong2 hv = *reinterpret_cast<const ulonglong2*>(&hs[e][k4*4]);
        aa = ffma2(hv.x, wA.x, aa); aa = ffma2(hv.y, wA.y, aa);
        ab = ffma2(hv.x, wB.x, ab); ab = ffma2(hv.y, wB.y, ab);
      }
      scr[e][lane]    = fmaxf(hsum2(aa) + ab1[lane],    0.f);
      scr[e][lane+32] = fmaxf(hsum2(ab) + ab1[lane+32], 0.f);
      __syncwarp();
      u64 t2a = 0ull;
      #pragma unroll
      for (int k4 = 0; k4 < 16; k4++){
        const ulonglong2 wv = *reinterpret_cast<const ulonglong2*>(aW2P + (k4*32 + lane)*4);
        const ulonglong2 sv = *reinterpret_cast<const ulonglong2*>(&scr[e][k4*4]);
        t2a = ffma2(sv.x, wv.x, t2a); t2a = ffma2(sv.y, wv.y, t2a);
      }
      t2 = fmaxf(hsum2(t2a) + ab2[lane], 0.f);
    }
    BAR_ELEM(e);

    if (wq == 1){
      u64 A01 = warpsum2(pack2(t2*aW3[lane*3+0], t2*aW3[lane*3+1]));
      float a2 = warpsum(t2*aW3[lane*3+2]);
      if (lane < 3){
        float v = (lane == 0) ? (lo2(A01) + ab3[0] + 0.1f*physs[e][0])
                : (lane == 1) ? (hi2(A01) + ab3[1] + 0.1f*physs[e][1])
                              : (a2       + ab3[2] + 0.1f*physs[e][2]);
        out[(b*T_STEPS + t)*3 + lane] = v;
      }
    }
    BAR_ELEM(e);   // elem may drift into next step's GAT (own slots only)
  }
}

extern "C" void kernel_launch(void* const* d_in, const int* in_sizes, int n_in,
                              void* d_out, int out_size)
{
  const int off = (n_in >= 30) ? 1 : 0;
  const int*   gesture_idx  = (const int*)  d_in[0];
  const float* demographics = (const float*)d_in[1];
  const float* emb_table = (const float*)d_in[2 + off];
  const float* dW1  = (const float*)d_in[3 + off];
  const float* db1  = (const float*)d_in[4 + off];
  const float* dW2  = (const float*)d_in[5 + off];
  const float* db2  = (const float*)d_in[6 + off];
  const float* jiW  = (const float*)d_in[7 + off];
  const float* jib  = (const float*)d_in[8 + off];
  const float* gatW = (const float*)d_in[9 + off];
  const float* gat_asrc = (const float*)d_in[10 + off];
  const float* gat_adst = (const float*)d_in[11 + off];
  const float* gat_b    = (const float*)d_in[12 + off];
  const float* ln_g = (const float*)d_in[13 + off];
  const float* ln_b = (const float*)d_in[14 + off];
  const float* W_ih = (const float*)d_in[15 + off];
  const float* W_hh = (const float*)d_in[16 + off];
  const float* b_ih = (const float*)d_in[17 + off];
  const float* b_hh = (const float*)d_in[18 + off];
  const float* pW1  = (const float*)d_in[19 + off];
  const float* pb1  = (const float*)d_in[20 + off];
  const float* pW2  = (const float*)d_in[21 + off];
  const float* pb2  = (const float*)d_in[22 + off];
  const float* aW1  = (const float*)d_in[23 + off];
  const float* ab1  = (const float*)d_in[24 + off];
  const float* aW2  = (const float*)d_in[25 + off];
  const float* ab2  = (const float*)d_in[26 + off];
  const float* aW3  = (const float*)d_in[27 + off];
  const float* ab3  = (const float*)d_in[28 + off];

  repack_kernel<<<128, 256>>>(gatW, W_ih, W_hh, pW1, aW1, aW2, b_ih, b_hh);
  vkc_kernel<<<512, 256>>>(gesture_idx, demographics, emb_table,
                           dW1, db1, dW2, db2, jiW, jib,
                           gat_asrc, gat_adst, gat_b, ln_g, ln_b,
                           pb1, pW2, pb2,
                           ab1, ab2,
                           aW3, ab3,
                           (float*)d_out);
}